// round 5
// baseline (speedup 1.0000x reference)
#include <cuda_runtime.h>
#include <cstdint>

// Problem constants (fixed by the reference)
#define B_      4
#define NQ_     1024
#define NC_     16384
#define D_      1024
#define TOPN    5
#define NCHUNK  8
#define CHUNK   (NC_ / NCHUNK)   // 2048
#define NROWS   (B_ * NQ_)       // 4096
#define NRESC   16               // candidates rescored in fp64 per row

// ---------------------------------------------------------------------------
// Scratch (no allocations allowed -> __device__ globals; referenced ONLY from
// device code).
// ---------------------------------------------------------------------------
__device__ float g_qproj[NROWS * D_];                     // 16 MB
__device__ float g_qsq[NROWS];
__device__ float g_csq[B_ * NC_];
__device__ unsigned long long g_cand[NROWS * NCHUNK * TOPN];

// ---------------------------------------------------------------------------
// Sorted-top5 insertion on packed keys: key = (float_bits(dist) << 32) | idx.
// ---------------------------------------------------------------------------
__device__ __forceinline__ void insert5(unsigned long long* run, unsigned long long key) {
    if (key < run[4]) {
        run[4] = key;
        if (run[4] < run[3]) { unsigned long long t = run[3]; run[3] = run[4]; run[4] = t; }
        if (run[3] < run[2]) { unsigned long long t = run[2]; run[2] = run[3]; run[3] = t; }
        if (run[2] < run[1]) { unsigned long long t = run[1]; run[1] = run[2]; run[2] = t; }
        if (run[1] < run[0]) { unsigned long long t = run[0]; run[0] = run[1]; run[1] = t; }
    }
}

// ---------------------------------------------------------------------------
// Kernel 1: q_proj[m][n] = sum_k Q[m][k] * W[n][k] + b[n]  (128x128x8 SGEMM)
// ---------------------------------------------------------------------------
__global__ __launch_bounds__(256, 2) void qproj_kernel(
    const float* __restrict__ Q, const float* __restrict__ W,
    const float* __restrict__ bias)
{
    __shared__ __align__(16) float As[8][132];
    __shared__ __align__(16) float Bs[8][132];

    const int t  = threadIdx.x;
    const int tx = t & 15, ty = t >> 4;
    const int m0 = blockIdx.y * 128, n0 = blockIdx.x * 128;
    const int lr = t >> 1;
    const int lk = (t & 1) * 4;

    const float* Ap = Q + (size_t)(m0 + lr) * D_ + lk;
    const float* Bp = W + (size_t)(n0 + lr) * D_ + lk;

    float acc[8][8];
    #pragma unroll
    for (int i = 0; i < 8; i++)
        #pragma unroll
        for (int j = 0; j < 8; j++) acc[i][j] = 0.0f;

    for (int k0 = 0; k0 < D_; k0 += 8) {
        float4 av = *(const float4*)(Ap + k0);
        float4 bv = *(const float4*)(Bp + k0);
        __syncthreads();
        As[lk + 0][lr] = av.x; As[lk + 1][lr] = av.y;
        As[lk + 2][lr] = av.z; As[lk + 3][lr] = av.w;
        Bs[lk + 0][lr] = bv.x; Bs[lk + 1][lr] = bv.y;
        Bs[lk + 2][lr] = bv.z; Bs[lk + 3][lr] = bv.w;
        __syncthreads();
        #pragma unroll
        for (int kk = 0; kk < 8; kk++) {
            float a[8], b[8];
            *(float4*)(a)     = *(const float4*)(&As[kk][ty * 8]);
            *(float4*)(a + 4) = *(const float4*)(&As[kk][ty * 8 + 4]);
            *(float4*)(b)     = *(const float4*)(&Bs[kk][tx * 8]);
            *(float4*)(b + 4) = *(const float4*)(&Bs[kk][tx * 8 + 4]);
            #pragma unroll
            for (int i = 0; i < 8; i++)
                #pragma unroll
                for (int j = 0; j < 8; j++)
                    acc[i][j] = fmaf(a[i], b[j], acc[i][j]);
        }
    }

    float bj[8];
    #pragma unroll
    for (int j = 0; j < 8; j++) bj[j] = bias[n0 + tx * 8 + j];
    #pragma unroll
    for (int i = 0; i < 8; i++) {
        int row = m0 + ty * 8 + i;
        float4 o0, o1;
        o0.x = __fadd_rn(acc[i][0], bj[0]); o0.y = __fadd_rn(acc[i][1], bj[1]);
        o0.z = __fadd_rn(acc[i][2], bj[2]); o0.w = __fadd_rn(acc[i][3], bj[3]);
        o1.x = __fadd_rn(acc[i][4], bj[4]); o1.y = __fadd_rn(acc[i][5], bj[5]);
        o1.z = __fadd_rn(acc[i][6], bj[6]); o1.w = __fadd_rn(acc[i][7], bj[7]);
        *(float4*)(g_qproj + (size_t)row * D_ + n0 + tx * 8)     = o0;
        *(float4*)(g_qproj + (size_t)row * D_ + n0 + tx * 8 + 4) = o1;
    }
}

// ---------------------------------------------------------------------------
// Kernel 2: squared row norms (screening only now — precision no longer
// ordering-critical; fp32 warp tree).
// ---------------------------------------------------------------------------
__device__ __forceinline__ void rowsq_body(
    const float* __restrict__ p, float* __restrict__ dst, int row)
{
    const int lane = threadIdx.x & 31;
    const float4* v4 = (const float4*)p;
    float s = 0.0f;
    #pragma unroll
    for (int it = 0; it < D_ / 4 / 32; it++) {
        float4 v = v4[lane + it * 32];
        s += v.x * v.x + v.y * v.y + v.z * v.z + v.w * v.w;
    }
    #pragma unroll
    for (int off = 16; off; off >>= 1) s += __shfl_xor_sync(0xffffffffu, s, off);
    if (lane == 0) dst[row] = s;
}

__global__ __launch_bounds__(256) void rowsq_q_kernel()
{
    int row = (blockIdx.x * blockDim.x + threadIdx.x) >> 5;
    if (row < NROWS) rowsq_body(g_qproj + (size_t)row * D_, g_qsq, row);
}

__global__ __launch_bounds__(256) void rowsq_c_kernel(const float* __restrict__ ctx)
{
    int row = (blockIdx.x * blockDim.x + threadIdx.x) >> 5;
    if (row < B_ * NC_) rowsq_body(ctx + (size_t)row * D_, g_csq, row);
}

// ---------------------------------------------------------------------------
// Kernel 3: fused cross-GEMM + distance + per-chunk top-5 (fp32 screening).
// ---------------------------------------------------------------------------
union DistSmem {
    struct { float As[8][132]; float Bs[8][132]; } g;   // 8448 B
    float dt[128][68];                                  // 34816 B
};

__global__ __launch_bounds__(256, 2) void dist_kernel(const float* __restrict__ ctx)
{
    __shared__ __align__(16) DistSmem sm;
    __shared__ float s_csq[CHUNK];

    const int t  = threadIdx.x;
    const int tx = t & 15, ty = t >> 4;
    const int ch = blockIdx.x;
    const int qb = blockIdx.y;
    const int b  = blockIdx.z;
    const int m0 = b * NQ_ + qb * 128;
    const int c0 = ch * CHUNK;

    const float* A     = g_qproj + (size_t)m0 * D_;
    const float* Bbase = ctx + ((size_t)b * NC_ + c0) * D_;

    for (int i = t; i < CHUNK; i += 256) s_csq[i] = g_csq[b * NC_ + c0 + i];

    const int lr = t >> 1;
    const int lk = (t & 1) * 4;

    unsigned long long run[5] = { ~0ull, ~0ull, ~0ull, ~0ull, ~0ull };
    const float qsq = (t < 128) ? g_qsq[m0 + t] : 0.0f;

    for (int nt = 0; nt < CHUNK / 128; nt++) {
        float acc[8][8];
        #pragma unroll
        for (int i = 0; i < 8; i++)
            #pragma unroll
            for (int j = 0; j < 8; j++) acc[i][j] = 0.0f;

        const float* Ap = A + (size_t)lr * D_ + lk;
        const float* Bp = Bbase + (size_t)(nt * 128 + lr) * D_ + lk;

        for (int k0 = 0; k0 < D_; k0 += 8) {
            float4 av = *(const float4*)(Ap + k0);
            float4 bv = *(const float4*)(Bp + k0);
            __syncthreads();
            sm.g.As[lk + 0][lr] = av.x; sm.g.As[lk + 1][lr] = av.y;
            sm.g.As[lk + 2][lr] = av.z; sm.g.As[lk + 3][lr] = av.w;
            sm.g.Bs[lk + 0][lr] = bv.x; sm.g.Bs[lk + 1][lr] = bv.y;
            sm.g.Bs[lk + 2][lr] = bv.z; sm.g.Bs[lk + 3][lr] = bv.w;
            __syncthreads();
            #pragma unroll
            for (int kk = 0; kk < 8; kk++) {
                float a[8], bb[8];
                *(float4*)(a)      = *(const float4*)(&sm.g.As[kk][ty * 8]);
                *(float4*)(a + 4)  = *(const float4*)(&sm.g.As[kk][ty * 8 + 4]);
                *(float4*)(bb)     = *(const float4*)(&sm.g.Bs[kk][tx * 8]);
                *(float4*)(bb + 4) = *(const float4*)(&sm.g.Bs[kk][tx * 8 + 4]);
                #pragma unroll
                for (int i = 0; i < 8; i++)
                    #pragma unroll
                    for (int j = 0; j < 8; j++)
                        acc[i][j] = fmaf(a[i], bb[j], acc[i][j]);
            }
        }
        __syncthreads();

        #pragma unroll
        for (int h = 0; h < 2; h++) {
            if ((tx >> 3) == h) {
                int cb = (tx & 7) * 8;
                #pragma unroll
                for (int i = 0; i < 8; i++) {
                    int r = ty * 8 + i;
                    *(float4*)(&sm.dt[r][cb])     = make_float4(acc[i][0], acc[i][1], acc[i][2], acc[i][3]);
                    *(float4*)(&sm.dt[r][cb + 4]) = make_float4(acc[i][4], acc[i][5], acc[i][6], acc[i][7]);
                }
            }
            __syncthreads();
            if (t < 128) {
                const int sbase = nt * 128 + h * 64;
                const int gbase = c0 + sbase;
                #pragma unroll 4
                for (int c = 0; c < 64; c++) {
                    float cross = sm.dt[t][c];
                    float d2 = fmaxf(qsq + s_csq[sbase + c] - 2.0f * cross, 0.0f);
                    float dist = sqrtf(d2);
                    unsigned long long key =
                        ((unsigned long long)__float_as_uint(dist) << 32) |
                        (unsigned)(gbase + c);
                    insert5(run, key);
                }
            }
            __syncthreads();
        }
    }

    if (t < 128) {
        size_t base = ((size_t)(m0 + t) * NCHUNK + ch) * TOPN;
        #pragma unroll
        for (int i = 0; i < TOPN; i++) g_cand[base + i] = run[i];
    }
}

// ---------------------------------------------------------------------------
// Kernel 4: merge per-chunk top-5s -> fp32 top-16 -> fp64 exact rescore of the
// 16 survivors -> final exact-ordered top-5.
// One block (256 threads = 8 warps) per q row.
// Output: out[0..20479] = distances, out[20480..40959] = indices as float.
// ---------------------------------------------------------------------------
__global__ __launch_bounds__(256) void rescore_kernel(
    const float* __restrict__ ctx, float* __restrict__ out, int out_size)
{
    __shared__ __align__(16) float s_q[D_];
    __shared__ int    s_idx[NRESC];
    __shared__ double s_d2[NRESC];

    const int row  = blockIdx.x;         // 0..NROWS-1
    const int b    = row / NQ_;
    const int t    = threadIdx.x;
    const int warp = t >> 5;
    const int lane = t & 31;

    // stage q row into smem
    {
        const float4* src = (const float4*)(g_qproj + (size_t)row * D_);
        float4* dst = (float4*)s_q;
        for (int i = t; i < D_ / 4; i += 256) dst[i] = src[i];
    }

    // thread 0: merge 40 chunk candidates into sorted fp32 top-16
    if (t == 0) {
        unsigned long long best[NRESC];
        #pragma unroll
        for (int i = 0; i < NRESC; i++) best[i] = ~0ull;
        const unsigned long long* p = g_cand + (size_t)row * NCHUNK * TOPN;
        for (int i = 0; i < NCHUNK * TOPN; i++) {
            unsigned long long key = p[i];
            if (key < best[NRESC - 1]) {
                int j = NRESC - 1;
                while (j > 0 && best[j - 1] > key) { best[j] = best[j - 1]; j--; }
                best[j] = key;
            }
        }
        #pragma unroll
        for (int i = 0; i < NRESC; i++) s_idx[i] = (int)(best[i] & 0xffffffffu);
    }
    __syncthreads();

    // 8 warps x 2 candidates each: exact fp64 d2 = sum_d (q_d - c_d)^2
    #pragma unroll
    for (int s = warp; s < NRESC; s += 8) {
        int idx = s_idx[s];
        const float* c = ctx + ((size_t)b * NC_ + idx) * D_;
        double acc = 0.0;
        #pragma unroll 4
        for (int e = lane; e < D_; e += 32) {
            double d = (double)s_q[e] - (double)c[e];
            acc = fma(d, d, acc);
        }
        #pragma unroll
        for (int off = 16; off; off >>= 1)
            acc += __shfl_xor_sync(0xffffffffu, acc, off);
        if (lane == 0) s_d2[s] = acc;
    }
    __syncthreads();

    // thread 0: selection-sort the 16 (d2, idx) pairs, emit top-5
    if (t == 0) {
        double d2l[NRESC]; int idl[NRESC];
        #pragma unroll
        for (int i = 0; i < NRESC; i++) { d2l[i] = s_d2[i]; idl[i] = s_idx[i]; }
        const bool write_idx = (out_size >= 2 * NROWS * TOPN);
        #pragma unroll
        for (int k = 0; k < TOPN; k++) {
            int m = k;
            for (int j = k + 1; j < NRESC; j++)
                if (d2l[j] < d2l[m] || (d2l[j] == d2l[m] && idl[j] < idl[m])) m = j;
            double td = d2l[m]; int ti = idl[m];
            d2l[m] = d2l[k]; idl[m] = idl[k];
            d2l[k] = td; idl[k] = ti;
            out[row * TOPN + k] = (float)sqrt(td);
            if (write_idx)
                out[NROWS * TOPN + row * TOPN + k] = (float)ti;
        }
    }
}

// ---------------------------------------------------------------------------
// Launch
// ---------------------------------------------------------------------------
extern "C" void kernel_launch(void* const* d_in, const int* in_sizes, int n_in,
                              void* d_out, int out_size)
{
    const float* Q    = (const float*)d_in[0];   // [4,1024,1024]
    const float* C    = (const float*)d_in[1];   // [4,16384,1024]
    const float* W    = (const float*)d_in[2];   // [1024,1024]
    const float* bias = (const float*)d_in[3];   // [1024]
    float* out = (float*)d_out;

    qproj_kernel<<<dim3(D_ / 128, NROWS / 128), 256>>>(Q, W, bias);
    rowsq_q_kernel<<<(NROWS * 32 + 255) / 256, 256>>>();
    rowsq_c_kernel<<<(B_ * NC_ * 32 + 255) / 256, 256>>>(C);
    dist_kernel<<<dim3(NCHUNK, NQ_ / 128, B_), 256>>>(C);
    rescore_kernel<<<NROWS, 256>>>(C, out, out_size);
}

// round 6
// speedup vs baseline: 2.7813x; 2.7813x over previous
#include <cuda_runtime.h>
#include <cuda_bf16.h>
#include <cstdint>

// Problem constants (fixed by the reference)
#define B_      4
#define NQ_     1024
#define NC_     16384
#define D_      1024
#define TOPN    5
#define NCHUNK  8
#define CHUNK   (NC_ / NCHUNK)   // 2048
#define NROWS   (B_ * NQ_)       // 4096
#define NRESC   16               // candidates rescored in fp64 per row

// ---------------------------------------------------------------------------
// Scratch (no allocations allowed -> __device__ globals, device-code refs only)
// ---------------------------------------------------------------------------
__device__ float          g_qproj[NROWS * D_];            // 16 MB fp32 q_proj
__device__ __nv_bfloat16  g_qp_bf[NROWS * D_];            // 8 MB bf16 q_proj
__device__ __nv_bfloat16  g_ctx_bf[(size_t)B_ * NC_ * D_];// 128 MB bf16 ctx
__device__ float          g_csq[B_ * NC_];
__device__ unsigned long long g_cand[NROWS * NCHUNK * TOPN];

// ---------------------------------------------------------------------------
// Sorted-top5 insertion on packed keys (smaller = better).
// ---------------------------------------------------------------------------
__device__ __forceinline__ void insert5(unsigned long long* run, unsigned long long key) {
    if (key < run[4]) {
        run[4] = key;
        if (run[4] < run[3]) { unsigned long long t = run[3]; run[3] = run[4]; run[4] = t; }
        if (run[3] < run[2]) { unsigned long long t = run[2]; run[2] = run[3]; run[3] = t; }
        if (run[2] < run[1]) { unsigned long long t = run[1]; run[1] = run[2]; run[2] = t; }
        if (run[1] < run[0]) { unsigned long long t = run[0]; run[0] = run[1]; run[1] = t; }
    }
}

__device__ __forceinline__ uint32_t smem_u32(const void* p) {
    uint32_t r;
    asm("{ .reg .u64 t; cvta.to.shared.u64 t, %1; cvt.u32.u64 %0, t; }" : "=r"(r) : "l"(p));
    return r;
}

// ---------------------------------------------------------------------------
// Kernel 1: q_proj = Q @ W^T + b (fp32 SIMT SGEMM). Also emits bf16 copy.
// Output distances derive from this fp32 result via fp64 rescore -> precision
// preserved; bf16 copy feeds the tensor-core screen only.
// ---------------------------------------------------------------------------
__global__ __launch_bounds__(256, 2) void qproj_kernel(
    const float* __restrict__ Q, const float* __restrict__ W,
    const float* __restrict__ bias)
{
    __shared__ __align__(16) float As[8][132];
    __shared__ __align__(16) float Bs[8][132];

    const int t  = threadIdx.x;
    const int tx = t & 15, ty = t >> 4;
    const int m0 = blockIdx.y * 128, n0 = blockIdx.x * 128;
    const int lr = t >> 1;
    const int lk = (t & 1) * 4;

    const float* Ap = Q + (size_t)(m0 + lr) * D_ + lk;
    const float* Bp = W + (size_t)(n0 + lr) * D_ + lk;

    float acc[8][8];
    #pragma unroll
    for (int i = 0; i < 8; i++)
        #pragma unroll
        for (int j = 0; j < 8; j++) acc[i][j] = 0.0f;

    for (int k0 = 0; k0 < D_; k0 += 8) {
        float4 av = *(const float4*)(Ap + k0);
        float4 bv = *(const float4*)(Bp + k0);
        __syncthreads();
        As[lk + 0][lr] = av.x; As[lk + 1][lr] = av.y;
        As[lk + 2][lr] = av.z; As[lk + 3][lr] = av.w;
        Bs[lk + 0][lr] = bv.x; Bs[lk + 1][lr] = bv.y;
        Bs[lk + 2][lr] = bv.z; Bs[lk + 3][lr] = bv.w;
        __syncthreads();
        #pragma unroll
        for (int kk = 0; kk < 8; kk++) {
            float a[8], b[8];
            *(float4*)(a)     = *(const float4*)(&As[kk][ty * 8]);
            *(float4*)(a + 4) = *(const float4*)(&As[kk][ty * 8 + 4]);
            *(float4*)(b)     = *(const float4*)(&Bs[kk][tx * 8]);
            *(float4*)(b + 4) = *(const float4*)(&Bs[kk][tx * 8 + 4]);
            #pragma unroll
            for (int i = 0; i < 8; i++)
                #pragma unroll
                for (int j = 0; j < 8; j++)
                    acc[i][j] = fmaf(a[i], b[j], acc[i][j]);
        }
    }

    float bj[8];
    #pragma unroll
    for (int j = 0; j < 8; j++) bj[j] = bias[n0 + tx * 8 + j];
    #pragma unroll
    for (int i = 0; i < 8; i++) {
        int row = m0 + ty * 8 + i;
        float o[8];
        #pragma unroll
        for (int j = 0; j < 8; j++) o[j] = __fadd_rn(acc[i][j], bj[j]);
        *(float4*)(g_qproj + (size_t)row * D_ + n0 + tx * 8)     = make_float4(o[0], o[1], o[2], o[3]);
        *(float4*)(g_qproj + (size_t)row * D_ + n0 + tx * 8 + 4) = make_float4(o[4], o[5], o[6], o[7]);
        __nv_bfloat162* dstb = (__nv_bfloat162*)(g_qp_bf + (size_t)row * D_ + n0 + tx * 8);
        dstb[0] = __floats2bfloat162_rn(o[0], o[1]);
        dstb[1] = __floats2bfloat162_rn(o[2], o[3]);
        dstb[2] = __floats2bfloat162_rn(o[4], o[5]);
        dstb[3] = __floats2bfloat162_rn(o[6], o[7]);
    }
}

// ---------------------------------------------------------------------------
// Kernel 2: ctx -> bf16 (8 floats per thread, 16B stores)
// ---------------------------------------------------------------------------
__global__ __launch_bounds__(256) void ctx2bf_kernel(const float* __restrict__ ctx)
{
    size_t i = (size_t)blockIdx.x * 256 + threadIdx.x;       // 8 elems each
    const size_t total = (size_t)B_ * NC_ * D_ / 8;          // 8M
    if (i >= total) return;
    float4 v0 = ((const float4*)ctx)[2 * i];
    float4 v1 = ((const float4*)ctx)[2 * i + 1];
    union { __nv_bfloat162 h[4]; uint4 u; } pk;
    pk.h[0] = __floats2bfloat162_rn(v0.x, v0.y);
    pk.h[1] = __floats2bfloat162_rn(v0.z, v0.w);
    pk.h[2] = __floats2bfloat162_rn(v1.x, v1.y);
    pk.h[3] = __floats2bfloat162_rn(v1.z, v1.w);
    ((uint4*)g_ctx_bf)[i] = pk.u;
}

// ---------------------------------------------------------------------------
// Kernel 3: context squared norms (fp32 screen input)
// ---------------------------------------------------------------------------
__global__ __launch_bounds__(256) void rowsq_c_kernel(const float* __restrict__ ctx)
{
    int row  = (blockIdx.x * blockDim.x + threadIdx.x) >> 5;
    int lane = threadIdx.x & 31;
    if (row >= B_ * NC_) return;
    const float4* p = (const float4*)(ctx + (size_t)row * D_);
    float s = 0.0f;
    #pragma unroll
    for (int it = 0; it < D_ / 4 / 32; it++) {
        float4 v = p[lane + it * 32];
        s += v.x * v.x + v.y * v.y + v.z * v.z + v.w * v.w;
    }
    #pragma unroll
    for (int off = 16; off; off >>= 1) s += __shfl_xor_sync(0xffffffffu, s, off);
    if (lane == 0) g_csq[row] = s;
}

// ---------------------------------------------------------------------------
// Kernel 4: bf16 tensor-core screen.
// CTA = (chunk of 2048 cands, 128 q rows, batch). 16 n-tiles of 128.
// 8 warps as 4(m) x 2(n); warp tile 32x64; mma.sync m16n8k16 bf16.
// Screen metric s = csq - 2*cross (qsq row-constant, dropped). Sign-corrected
// bit key + candidate idx; per-row top-5 per chunk -> g_cand.
// smem: A/B tiles 128 rows x 32 bf16, row stride 5x16B (pad) -> conflict-free
// ldmatrix & B-frag LDS. Epilogue staged in 32-col passes through dt.
// ---------------------------------------------------------------------------
__global__ __launch_bounds__(256) void screen_kernel()
{
    __shared__ __align__(16) uint4 sA[128 * 5];   // 10240 B
    __shared__ __align__(16) uint4 sB[128 * 5];   // 10240 B
    __shared__ float dt[128][33];                 // 16896 B
    __shared__ float s_csq[CHUNK];                // 8192 B

    const int t    = threadIdx.x;
    const int lane = t & 31;
    const int w    = t >> 5;
    const int wm   = w >> 1;        // 0..3 (m)
    const int wn   = w & 1;         // 0..1 (n)
    const int ch   = blockIdx.x;    // chunk
    const int qb   = blockIdx.y;    // q block
    const int b    = blockIdx.z;    // batch
    const int m0   = b * NQ_ + qb * 128;
    const int c0   = ch * CHUNK;

    for (int i = t; i < CHUNK; i += 256) s_csq[i] = g_csq[b * NC_ + c0 + i];

    const uint32_t sA_base = smem_u32(sA);
    const char* sB_c = (const char*)sB;

    unsigned long long run[5] = { ~0ull, ~0ull, ~0ull, ~0ull, ~0ull };

    // ldmatrix lane roles (constant across loop)
    const int lm_row   = lane & 15;         // row within 16-row frag
    const int lm_chalf = lane >> 4;         // 0/1: k-chunk half

    for (int nt = 0; nt < CHUNK / 128; nt++) {
        float acc[2][8][4];
        #pragma unroll
        for (int fm = 0; fm < 2; fm++)
            #pragma unroll
            for (int fn = 0; fn < 8; fn++)
                #pragma unroll
                for (int v = 0; v < 4; v++) acc[fm][fn][v] = 0.0f;

        const size_t arow = (size_t)m0;                       // q rows base
        const size_t brow = (size_t)b * NC_ + c0 + nt * 128;  // cand rows base

        for (int k0 = 0; k0 < D_; k0 += 32) {
            __syncthreads();   // prior mma reads of sA/sB done
            {
                int q = t;                 // first 256 of 512 16B-chunks
                int r = q >> 2, c = q & 3;
                sA[r * 5 + c] = *(const uint4*)&g_qp_bf[(arow + r) * D_ + k0 + c * 8];
                sB[r * 5 + c] = *(const uint4*)&g_ctx_bf[(brow + r) * D_ + k0 + c * 8];
                q = t + 256;
                r = q >> 2; c = q & 3;
                sA[r * 5 + c] = *(const uint4*)&g_qp_bf[(arow + r) * D_ + k0 + c * 8];
                sB[r * 5 + c] = *(const uint4*)&g_ctx_bf[(brow + r) * D_ + k0 + c * 8];
            }
            __syncthreads();

            #pragma unroll
            for (int kh = 0; kh < 2; kh++) {
                // A fragments via ldmatrix.x4 (16x16 per m-frag)
                uint32_t a[2][4];
                #pragma unroll
                for (int fm = 0; fm < 2; fm++) {
                    int row = wm * 32 + fm * 16 + lm_row;
                    int chk = kh * 2 + lm_chalf;
                    uint32_t addr = sA_base + (uint32_t)((row * 5 + chk) * 16);
                    asm volatile(
                        "ldmatrix.sync.aligned.m8n8.x4.shared.b16 {%0,%1,%2,%3}, [%4];"
                        : "=r"(a[fm][0]), "=r"(a[fm][1]), "=r"(a[fm][2]), "=r"(a[fm][3])
                        : "r"(addr));
                }
                // B fragments manual (conflict-free 4B LDS), then mma
                #pragma unroll
                for (int fn = 0; fn < 8; fn++) {
                    int n = wn * 64 + fn * 8 + (lane >> 2);
                    const char* bp = sB_c + n * 80 + kh * 32 + (lane & 3) * 4;
                    uint32_t b0 = *(const uint32_t*)bp;
                    uint32_t b1 = *(const uint32_t*)(bp + 16);
                    asm volatile(
                        "mma.sync.aligned.m16n8k16.row.col.f32.bf16.bf16.f32 "
                        "{%0,%1,%2,%3},{%4,%5,%6,%7},{%8,%9},{%0,%1,%2,%3};"
                        : "+f"(acc[0][fn][0]), "+f"(acc[0][fn][1]),
                          "+f"(acc[0][fn][2]), "+f"(acc[0][fn][3])
                        : "r"(a[0][0]), "r"(a[0][1]), "r"(a[0][2]), "r"(a[0][3]),
                          "r"(b0), "r"(b1));
                    asm volatile(
                        "mma.sync.aligned.m16n8k16.row.col.f32.bf16.bf16.f32 "
                        "{%0,%1,%2,%3},{%4,%5,%6,%7},{%8,%9},{%0,%1,%2,%3};"
                        : "+f"(acc[1][fn][0]), "+f"(acc[1][fn][1]),
                          "+f"(acc[1][fn][2]), "+f"(acc[1][fn][3])
                        : "r"(a[1][0]), "r"(a[1][1]), "r"(a[1][2]), "r"(a[1][3]),
                          "r"(b0), "r"(b1));
                }
            }
        }

        // Epilogue: 4 passes of 32 cols. Pass p: warps with wn == p>>1 write
        // frag_n group (p&1)*4 .. +3; then 128 threads scan one row each.
        #pragma unroll
        for (int p = 0; p < 4; p++) {
            if (wn == (p >> 1)) {
                int fnb = (p & 1) * 4;
                #pragma unroll
                for (int fm = 0; fm < 2; fm++) {
                    int r0 = wm * 32 + fm * 16 + (lane >> 2);
                    #pragma unroll
                    for (int ff = 0; ff < 4; ff++) {
                        int cl = ff * 8 + (lane & 3) * 2;
                        dt[r0][cl]         = acc[fm][fnb + ff][0];
                        dt[r0][cl + 1]     = acc[fm][fnb + ff][1];
                        dt[r0 + 8][cl]     = acc[fm][fnb + ff][2];
                        dt[r0 + 8][cl + 1] = acc[fm][fnb + ff][3];
                    }
                }
            }
            __syncthreads();
            if (t < 128) {
                int base = nt * 128 + p * 32;
                #pragma unroll 4
                for (int c = 0; c < 32; c++) {
                    float s = __fmaf_rn(-2.0f, dt[t][c], s_csq[base + c]);
                    unsigned u = __float_as_uint(s);
                    u ^= (unsigned)((int)u >> 31) | 0x80000000u;   // order-preserving
                    unsigned long long key =
                        ((unsigned long long)u << 32) | (unsigned)(c0 + base + c);
                    insert5(run, key);
                }
            }
            __syncthreads();
        }
    }

    if (t < 128) {
        size_t base = ((size_t)(m0 + t) * NCHUNK + ch) * TOPN;
        #pragma unroll
        for (int i = 0; i < TOPN; i++) g_cand[base + i] = run[i];
    }
}

// ---------------------------------------------------------------------------
// Kernel 5: merge 40 screened candidates -> top-16 -> exact fp64 rescore ->
// final top-5 (exact ordering, exact distances). One block per q row.
// Output: out[0..20479] = distances, out[20480..40959] = indices as float.
// ---------------------------------------------------------------------------
__global__ __launch_bounds__(256) void rescore_kernel(
    const float* __restrict__ ctx, float* __restrict__ out, int out_size)
{
    __shared__ __align__(16) float s_q[D_];
    __shared__ int    s_idx[NRESC];
    __shared__ double s_d2[NRESC];

    const int row  = blockIdx.x;
    const int b    = row / NQ_;
    const int t    = threadIdx.x;
    const int warp = t >> 5;
    const int lane = t & 31;

    {
        const float4* src = (const float4*)(g_qproj + (size_t)row * D_);
        float4* dst = (float4*)s_q;
        for (int i = t; i < D_ / 4; i += 256) dst[i] = src[i];
    }

    if (t == 0) {
        unsigned long long best[NRESC];
        #pragma unroll
        for (int i = 0; i < NRESC; i++) best[i] = ~0ull;
        const unsigned long long* p = g_cand + (size_t)row * NCHUNK * TOPN;
        for (int i = 0; i < NCHUNK * TOPN; i++) {
            unsigned long long key = p[i];
            if (key < best[NRESC - 1]) {
                int j = NRESC - 1;
                while (j > 0 && best[j - 1] > key) { best[j] = best[j - 1]; j--; }
                best[j] = key;
            }
        }
        #pragma unroll
        for (int i = 0; i < NRESC; i++) s_idx[i] = (int)(best[i] & 0xffffffffu);
    }
    __syncthreads();

    #pragma unroll
    for (int s = warp; s < NRESC; s += 8) {
        int idx = s_idx[s];
        const float* c = ctx + ((size_t)b * NC_ + idx) * D_;
        double acc = 0.0;
        #pragma unroll 4
        for (int e = lane; e < D_; e += 32) {
            double d = (double)s_q[e] - (double)c[e];
            acc = fma(d, d, acc);
        }
        #pragma unroll
        for (int off = 16; off; off >>= 1)
            acc += __shfl_xor_sync(0xffffffffu, acc, off);
        if (lane == 0) s_d2[s] = acc;
    }
    __syncthreads();

    if (t == 0) {
        double d2l[NRESC]; int idl[NRESC];
        #pragma unroll
        for (int i = 0; i < NRESC; i++) { d2l[i] = s_d2[i]; idl[i] = s_idx[i]; }
        const bool write_idx = (out_size >= 2 * NROWS * TOPN);
        #pragma unroll
        for (int k = 0; k < TOPN; k++) {
            int m = k;
            for (int j = k + 1; j < NRESC; j++)
                if (d2l[j] < d2l[m] || (d2l[j] == d2l[m] && idl[j] < idl[m])) m = j;
            double td = d2l[m]; int ti = idl[m];
            d2l[m] = d2l[k]; idl[m] = idl[k];
            d2l[k] = td; idl[k] = ti;
            out[row * TOPN + k] = (float)sqrt(td);
            if (write_idx)
                out[NROWS * TOPN + row * TOPN + k] = (float)ti;
        }
    }
}

// ---------------------------------------------------------------------------
// Launch
// ---------------------------------------------------------------------------
extern "C" void kernel_launch(void* const* d_in, const int* in_sizes, int n_in,
                              void* d_out, int out_size)
{
    const float* Q    = (const float*)d_in[0];   // [4,1024,1024]
    const float* C    = (const float*)d_in[1];   // [4,16384,1024]
    const float* W    = (const float*)d_in[2];   // [1024,1024]
    const float* bias = (const float*)d_in[3];   // [1024]
    float* out = (float*)d_out;

    qproj_kernel<<<dim3(D_ / 128, NROWS / 128), 256>>>(Q, W, bias);
    ctx2bf_kernel<<<(unsigned)(((size_t)B_ * NC_ * D_ / 8 + 255) / 256), 256>>>(C);
    rowsq_c_kernel<<<(B_ * NC_ * 32 + 255) / 256, 256>>>(C);
    screen_kernel<<<dim3(NCHUNK, NQ_ / 128, B_), 256>>>();
    rescore_kernel<<<NROWS, 256>>>(C, out, out_size);
}

// round 7
// speedup vs baseline: 3.2203x; 1.1578x over previous
#include <cuda_runtime.h>
#include <cuda_bf16.h>
#include <cstdint>

// Problem constants (fixed by the reference)
#define B_      4
#define NQ_     1024
#define NC_     16384
#define D_      1024
#define TOPN    5
#define NCHUNK  8
#define CHUNK   (NC_ / NCHUNK)   // 2048
#define NROWS   (B_ * NQ_)       // 4096
#define NRESC   16               // candidates rescored in fp64 per row

// Screen tiling
#define KT      64                        // k-tile (bf16 elems)
#define NKT     (D_ / KT)                 // 16
#define ROWB    144                       // bytes/row in smem tile (8 chunks + pad)
#define STG_A   (128 * ROWB)              // 18432 B per A tile
#define STG     (2 * STG_A)               // 36864 B per stage (A+B)
#define SM_DT   (2 * STG)                 // 73728: dt offset
#define SM_CSQ  (SM_DT + 128 * 33 * 4)    // 90624: csq offset
#define SM_SCRN (SM_CSQ + CHUNK * 4)      // 98816 total dynamic smem

// ---------------------------------------------------------------------------
// Scratch (no allocations allowed -> __device__ globals, device-code refs only)
// ---------------------------------------------------------------------------
__device__ float          g_qproj[NROWS * D_];            // fp32 q_proj
__device__ __nv_bfloat16  g_qp_bf[NROWS * D_];            // bf16 q_proj
__device__ __nv_bfloat16  g_ctx_bf[(size_t)B_ * NC_ * D_];// bf16 ctx
__device__ float          g_csq[B_ * NC_];
__device__ unsigned long long g_cand[NROWS * NCHUNK * TOPN];

// ---------------------------------------------------------------------------
__device__ __forceinline__ void insert5(unsigned long long* run, unsigned long long key) {
    if (key < run[4]) {
        run[4] = key;
        if (run[4] < run[3]) { unsigned long long t = run[3]; run[3] = run[4]; run[4] = t; }
        if (run[3] < run[2]) { unsigned long long t = run[2]; run[2] = run[3]; run[3] = t; }
        if (run[2] < run[1]) { unsigned long long t = run[1]; run[1] = run[2]; run[2] = t; }
        if (run[1] < run[0]) { unsigned long long t = run[0]; run[0] = run[1]; run[1] = t; }
    }
}

__device__ __forceinline__ uint32_t smem_u32(const void* p) {
    uint32_t r;
    asm("{ .reg .u64 t; cvta.to.shared.u64 t, %1; cvt.u32.u64 %0, t; }" : "=r"(r) : "l"(p));
    return r;
}

__device__ __forceinline__ void cpa16(uint32_t dst, const void* src) {
    asm volatile("cp.async.cg.shared.global [%0], [%1], 16;" :: "r"(dst), "l"(src));
}

// ---------------------------------------------------------------------------
// Kernel 1: q_proj = Q @ W^T + b (fp32 SIMT SGEMM) + bf16 copy for the screen.
// ---------------------------------------------------------------------------
__global__ __launch_bounds__(256, 2) void qproj_kernel(
    const float* __restrict__ Q, const float* __restrict__ W,
    const float* __restrict__ bias)
{
    __shared__ __align__(16) float As[8][132];
    __shared__ __align__(16) float Bs[8][132];

    const int t  = threadIdx.x;
    const int tx = t & 15, ty = t >> 4;
    const int m0 = blockIdx.y * 128, n0 = blockIdx.x * 128;
    const int lr = t >> 1;
    const int lk = (t & 1) * 4;

    const float* Ap = Q + (size_t)(m0 + lr) * D_ + lk;
    const float* Bp = W + (size_t)(n0 + lr) * D_ + lk;

    float acc[8][8];
    #pragma unroll
    for (int i = 0; i < 8; i++)
        #pragma unroll
        for (int j = 0; j < 8; j++) acc[i][j] = 0.0f;

    for (int k0 = 0; k0 < D_; k0 += 8) {
        float4 av = *(const float4*)(Ap + k0);
        float4 bv = *(const float4*)(Bp + k0);
        __syncthreads();
        As[lk + 0][lr] = av.x; As[lk + 1][lr] = av.y;
        As[lk + 2][lr] = av.z; As[lk + 3][lr] = av.w;
        Bs[lk + 0][lr] = bv.x; Bs[lk + 1][lr] = bv.y;
        Bs[lk + 2][lr] = bv.z; Bs[lk + 3][lr] = bv.w;
        __syncthreads();
        #pragma unroll
        for (int kk = 0; kk < 8; kk++) {
            float a[8], b[8];
            *(float4*)(a)     = *(const float4*)(&As[kk][ty * 8]);
            *(float4*)(a + 4) = *(const float4*)(&As[kk][ty * 8 + 4]);
            *(float4*)(b)     = *(const float4*)(&Bs[kk][tx * 8]);
            *(float4*)(b + 4) = *(const float4*)(&Bs[kk][tx * 8 + 4]);
            #pragma unroll
            for (int i = 0; i < 8; i++)
                #pragma unroll
                for (int j = 0; j < 8; j++)
                    acc[i][j] = fmaf(a[i], b[j], acc[i][j]);
        }
    }

    float bj[8];
    #pragma unroll
    for (int j = 0; j < 8; j++) bj[j] = bias[n0 + tx * 8 + j];
    #pragma unroll
    for (int i = 0; i < 8; i++) {
        int row = m0 + ty * 8 + i;
        float o[8];
        #pragma unroll
        for (int j = 0; j < 8; j++) o[j] = __fadd_rn(acc[i][j], bj[j]);
        *(float4*)(g_qproj + (size_t)row * D_ + n0 + tx * 8)     = make_float4(o[0], o[1], o[2], o[3]);
        *(float4*)(g_qproj + (size_t)row * D_ + n0 + tx * 8 + 4) = make_float4(o[4], o[5], o[6], o[7]);
        __nv_bfloat162* dstb = (__nv_bfloat162*)(g_qp_bf + (size_t)row * D_ + n0 + tx * 8);
        dstb[0] = __floats2bfloat162_rn(o[0], o[1]);
        dstb[1] = __floats2bfloat162_rn(o[2], o[3]);
        dstb[2] = __floats2bfloat162_rn(o[4], o[5]);
        dstb[3] = __floats2bfloat162_rn(o[6], o[7]);
    }
}

// ---------------------------------------------------------------------------
// Kernel 2 (fused): one pass over ctx -> bf16 copy + squared row norms.
// One warp per row.
// ---------------------------------------------------------------------------
__global__ __launch_bounds__(256) void ctxprep_kernel(const float* __restrict__ ctx)
{
    int row  = (blockIdx.x * blockDim.x + threadIdx.x) >> 5;
    int lane = threadIdx.x & 31;
    if (row >= B_ * NC_) return;
    const float4* p = (const float4*)(ctx + (size_t)row * D_);
    uint2* ob = (uint2*)(g_ctx_bf + (size_t)row * D_);
    float s = 0.0f;
    #pragma unroll
    for (int it = 0; it < D_ / 4 / 32; it++) {
        float4 v = p[lane + it * 32];
        s += v.x * v.x + v.y * v.y + v.z * v.z + v.w * v.w;
        union { __nv_bfloat162 h[2]; uint2 u; } pk;
        pk.h[0] = __floats2bfloat162_rn(v.x, v.y);
        pk.h[1] = __floats2bfloat162_rn(v.z, v.w);
        ob[lane + it * 32] = pk.u;
    }
    #pragma unroll
    for (int off = 16; off; off >>= 1) s += __shfl_xor_sync(0xffffffffu, s, off);
    if (lane == 0) g_csq[row] = s;
}

// ---------------------------------------------------------------------------
// Kernel 3: bf16 tensor-core screen, 2-stage cp.async pipeline.
// CTA = (chunk, 128 q rows, batch); 16 n-tiles of 128 cands; k-tile 64.
// Warps: 2(m) x 4(n), warp tile 64x32, mma.sync m16n8k16 bf16.
// smem rows padded to 144B (9 x 16B chunks; stride 9 coprime-ish with banks
// -> ldmatrix + B-frag LDS conflict-free).
// Screen metric s = csq - 2*cross (qsq row-constant, dropped).
// ---------------------------------------------------------------------------
__global__ __launch_bounds__(256) void screen_kernel()
{
    extern __shared__ __align__(16) char dsm[];
    float (*dt)[33] = (float(*)[33])(dsm + SM_DT);
    float* s_csq    = (float*)(dsm + SM_CSQ);
    const uint32_t smb = smem_u32(dsm);

    const int t    = threadIdx.x;
    const int lane = t & 31;
    const int w    = t >> 5;
    const int wm   = w >> 2;        // 0..1 (m half)
    const int wn   = w & 3;         // 0..3 (n quarter)
    const int ch   = blockIdx.x;
    const int qb   = blockIdx.y;
    const int b    = blockIdx.z;
    const int m0   = b * NQ_ + qb * 128;
    const int c0   = ch * CHUNK;

    for (int i = t; i < CHUNK; i += 256) s_csq[i] = g_csq[b * NC_ + c0 + i];

    // per-thread load slots: 4 A chunks + 4 B chunks per stage
    int ldr[4], ldc[4];
    #pragma unroll
    for (int i = 0; i < 4; i++) {
        int c = t + i * 256;        // 0..1023
        ldr[i] = c >> 3;            // row 0..127
        ldc[i] = c & 7;             // chunk 0..7
    }

    const int lm_row  = lane & 15;
    const int lm_half = lane >> 4;

    unsigned long long run[5] = { ~0ull, ~0ull, ~0ull, ~0ull, ~0ull };

    const __nv_bfloat16* gA = g_qp_bf + (size_t)m0 * D_;

    for (int nt = 0; nt < CHUNK / 128; nt++) {
        const __nv_bfloat16* gB = g_ctx_bf + ((size_t)b * NC_ + c0 + nt * 128) * D_;

        float acc[4][4][4];
        #pragma unroll
        for (int fm = 0; fm < 4; fm++)
            #pragma unroll
            for (int fn = 0; fn < 4; fn++)
                #pragma unroll
                for (int v = 0; v < 4; v++) acc[fm][fn][v] = 0.0f;

        // prologue: stage 0 into buffer 0
        #pragma unroll
        for (int i = 0; i < 4; i++) {
            cpa16(smb + ldr[i] * ROWB + ldc[i] * 16,
                  gA + (size_t)ldr[i] * D_ + ldc[i] * 8);
            cpa16(smb + STG_A + ldr[i] * ROWB + ldc[i] * 16,
                  gB + (size_t)ldr[i] * D_ + ldc[i] * 8);
        }
        asm volatile("cp.async.commit_group;");

        for (int kt = 0; kt < NKT; kt++) {
            asm volatile("cp.async.wait_group 0;");
            __syncthreads();
            if (kt + 1 < NKT) {
                uint32_t sb = smb + ((kt + 1) & 1) * STG;
                int koff = (kt + 1) * KT;
                #pragma unroll
                for (int i = 0; i < 4; i++) {
                    cpa16(sb + ldr[i] * ROWB + ldc[i] * 16,
                          gA + (size_t)ldr[i] * D_ + koff + ldc[i] * 8);
                    cpa16(sb + STG_A + ldr[i] * ROWB + ldc[i] * 16,
                          gB + (size_t)ldr[i] * D_ + koff + ldc[i] * 8);
                }
                asm volatile("cp.async.commit_group;");
            }
            const uint32_t bufA = smb + (kt & 1) * STG;
            const uint32_t bufB = bufA + STG_A;

            #pragma unroll
            for (int kh = 0; kh < 4; kh++) {
                uint32_t a[4][4];
                #pragma unroll
                for (int fm = 0; fm < 4; fm++) {
                    int row = wm * 64 + fm * 16 + lm_row;
                    uint32_t addr = bufA + (uint32_t)(row * ROWB + (kh * 2 + lm_half) * 16);
                    asm volatile(
                        "ldmatrix.sync.aligned.m8n8.x4.shared.b16 {%0,%1,%2,%3}, [%4];"
                        : "=r"(a[fm][0]), "=r"(a[fm][1]), "=r"(a[fm][2]), "=r"(a[fm][3])
                        : "r"(addr));
                }
                #pragma unroll
                for (int fn = 0; fn < 4; fn++) {
                    int n = wn * 32 + fn * 8 + (lane >> 2);
                    uint32_t baddr = bufB + (uint32_t)(n * ROWB + kh * 32 + (lane & 3) * 4);
                    uint32_t b0, b1;
                    asm volatile("ld.shared.b32 %0, [%1];" : "=r"(b0) : "r"(baddr));
                    asm volatile("ld.shared.b32 %0, [%1];" : "=r"(b1) : "r"(baddr + 16));
                    #pragma unroll
                    for (int fm = 0; fm < 4; fm++) {
                        asm volatile(
                            "mma.sync.aligned.m16n8k16.row.col.f32.bf16.bf16.f32 "
                            "{%0,%1,%2,%3},{%4,%5,%6,%7},{%8,%9},{%0,%1,%2,%3};"
                            : "+f"(acc[fm][fn][0]), "+f"(acc[fm][fn][1]),
                              "+f"(acc[fm][fn][2]), "+f"(acc[fm][fn][3])
                            : "r"(a[fm][0]), "r"(a[fm][1]), "r"(a[fm][2]), "r"(a[fm][3]),
                              "r"(b0), "r"(b1));
                    }
                }
            }
        }

        // Epilogue: 4 passes of 32 cols. Pass p: warps with wn==p stage their
        // 64x32 sub-tiles; 128 threads then scan one row each.
        #pragma unroll
        for (int p = 0; p < 4; p++) {
            if (wn == p) {
                #pragma unroll
                for (int fm = 0; fm < 4; fm++) {
                    int r0 = wm * 64 + fm * 16 + (lane >> 2);
                    #pragma unroll
                    for (int ff = 0; ff < 4; ff++) {
                        int cl = ff * 8 + (lane & 3) * 2;
                        dt[r0][cl]         = acc[fm][ff][0];
                        dt[r0][cl + 1]     = acc[fm][ff][1];
                        dt[r0 + 8][cl]     = acc[fm][ff][2];
                        dt[r0 + 8][cl + 1] = acc[fm][ff][3];
                    }
                }
            }
            __syncthreads();
            if (t < 128) {
                int base = nt * 128 + p * 32;
                #pragma unroll 8
                for (int c = 0; c < 32; c++) {
                    float s = __fmaf_rn(-2.0f, dt[t][c], s_csq[base + c]);
                    unsigned u = __float_as_uint(s);
                    u ^= (unsigned)((int)u >> 31) | 0x80000000u;
                    unsigned long long key =
                        ((unsigned long long)u << 32) | (unsigned)(c0 + base + c);
                    insert5(run, key);
                }
            }
            __syncthreads();
        }
    }

    if (t < 128) {
        size_t base = ((size_t)(m0 + t) * NCHUNK + ch) * TOPN;
        #pragma unroll
        for (int i = 0; i < TOPN; i++) g_cand[base + i] = run[i];
    }
}

// ---------------------------------------------------------------------------
// Kernel 4: merge 40 screened candidates -> top-16 -> exact fp64 rescore ->
// final top-5. One block per q row.
// Output: out[0..20479] = distances, out[20480..40959] = indices as float.
// ---------------------------------------------------------------------------
__global__ __launch_bounds__(256) void rescore_kernel(
    const float* __restrict__ ctx, float* __restrict__ out, int out_size)
{
    __shared__ __align__(16) float s_q[D_];
    __shared__ int    s_idx[NRESC];
    __shared__ double s_d2[NRESC];

    const int row  = blockIdx.x;
    const int b    = row / NQ_;
    const int t    = threadIdx.x;
    const int warp = t >> 5;
    const int lane = t & 31;

    {
        const float4* src = (const float4*)(g_qproj + (size_t)row * D_);
        float4* dst = (float4*)s_q;
        for (int i = t; i < D_ / 4; i += 256) dst[i] = src[i];
    }

    if (t == 0) {
        unsigned long long best[NRESC];
        #pragma unroll
        for (int i = 0; i < NRESC; i++) best[i] = ~0ull;
        const unsigned long long* p = g_cand + (size_t)row * NCHUNK * TOPN;
        for (int i = 0; i < NCHUNK * TOPN; i++) {
            unsigned long long key = p[i];
            if (key < best[NRESC - 1]) {
                int j = NRESC - 1;
                while (j > 0 && best[j - 1] > key) { best[j] = best[j - 1]; j--; }
                best[j] = key;
            }
        }
        #pragma unroll
        for (int i = 0; i < NRESC; i++) s_idx[i] = (int)(best[i] & 0xffffffffu);
    }
    __syncthreads();

    #pragma unroll
    for (int s = warp; s < NRESC; s += 8) {
        int idx = s_idx[s];
        const float* c = ctx + ((size_t)b * NC_ + idx) * D_;
        double acc = 0.0;
        #pragma unroll 4
        for (int e = lane; e < D_; e += 32) {
            double d = (double)s_q[e] - (double)c[e];
            acc = fma(d, d, acc);
        }
        #pragma unroll
        for (int off = 16; off; off >>= 1)
            acc += __shfl_xor_sync(0xffffffffu, acc, off);
        if (lane == 0) s_d2[s] = acc;
    }
    __syncthreads();

    if (t == 0) {
        double d2l[NRESC]; int idl[NRESC];
        #pragma unroll
        for (int i = 0; i < NRESC; i++) { d2l[i] = s_d2[i]; idl[i] = s_idx[i]; }
        const bool write_idx = (out_size >= 2 * NROWS * TOPN);
        #pragma unroll
        for (int k = 0; k < TOPN; k++) {
            int m = k;
            for (int j = k + 1; j < NRESC; j++)
                if (d2l[j] < d2l[m] || (d2l[j] == d2l[m] && idl[j] < idl[m])) m = j;
            double td = d2l[m]; int ti = idl[m];
            d2l[m] = d2l[k]; idl[m] = idl[k];
            d2l[k] = td; idl[k] = ti;
            out[row * TOPN + k] = (float)sqrt(td);
            if (write_idx)
                out[NROWS * TOPN + row * TOPN + k] = (float)ti;
        }
    }
}

// ---------------------------------------------------------------------------
// Launch
// ---------------------------------------------------------------------------
extern "C" void kernel_launch(void* const* d_in, const int* in_sizes, int n_in,
                              void* d_out, int out_size)
{
    const float* Q    = (const float*)d_in[0];   // [4,1024,1024]
    const float* C    = (const float*)d_in[1];   // [4,16384,1024]
    const float* W    = (const float*)d_in[2];   // [1024,1024]
    const float* bias = (const float*)d_in[3];   // [1024]
    float* out = (float*)d_out;

    cudaFuncSetAttribute(screen_kernel,
                         cudaFuncAttributeMaxDynamicSharedMemorySize, SM_SCRN);

    qproj_kernel<<<dim3(D_ / 128, NROWS / 128), 256>>>(Q, W, bias);
    ctxprep_kernel<<<(B_ * NC_ * 32 + 255) / 256, 256>>>(C);
    screen_kernel<<<dim3(NCHUNK, NQ_ / 128, B_), 256, SM_SCRN>>>();
    rescore_kernel<<<NROWS, 256>>>(C, out, out_size);
}